// round 1
// baseline (speedup 1.0000x reference)
#include <cuda_runtime.h>
#include <math.h>

#define NF    64
#define NL    5
#define NMZI  2016
#define NCLS  12
#define TILE_R 128
#define TPB   256

#define CHALF 0.70710678118654752f
#define GAM   0.05f
#define GAM2  0.0025f

// scratch (device globals: allocation-free)
__device__ float4 g_trig[NL * NMZI];           // (cos th, sin th, cos phi, sin phi)
__device__ float2 g_UT[NL * NF * NF];          // U^T per layer: g_UT[l][j][c] = U[c][j]

// ---------------------------------------------------------------------------
// Kernel A0: all sincos in parallel
// ---------------------------------------------------------------------------
__global__ void trig_kernel(const float* __restrict__ mzi) {
    int idx = blockIdx.x * blockDim.x + threadIdx.x;
    if (idx >= NL * NMZI) return;
    int l = idx / NMZI, k = idx - l * NMZI;
    float th = mzi[l * (2 * NMZI) + 2 * k];
    float ph = mzi[l * (2 * NMZI) + 2 * k + 1];
    float st, ct, sp, cp;
    sincosf(th, &st, &ct);
    sincosf(ph, &sp, &cp);
    g_trig[idx] = make_float4(ct, st, cp, sp);
}

// ---------------------------------------------------------------------------
// Kernel A: build the 5 unitaries. One block per layer, thread t owns column t.
// The scan's active row i is kept in registers (ui) across the run of equal i,
// so the serial chain is FMA-latency, not LDS+STS latency.
// ---------------------------------------------------------------------------
__global__ void build_unitaries(const float* __restrict__ ophase) {
    __shared__ float2 sU[NF * NF];       // sU[r*64 + c]
    const int l = blockIdx.x;
    const int t = threadIdx.x;           // column index
    for (int idx = t; idx < NF * NF; idx += 64) {
        int r = idx >> 6, c = idx & 63;
        sU[idx] = make_float2(r == c ? 1.f : 0.f, 0.f);
    }
    __syncthreads();

    int i = 0, j = 1;
    float2 ui = sU[t];                   // row 0 of identity
    const float4* trig = g_trig + l * NMZI;
    for (int k = 0; k < NMZI; ++k) {
        float4 tr = trig[k];             // ct, st, cp, sp
        float2 uj = sU[j * NF + t];
        // e^{i phi} * uj
        float epx = tr.z * uj.x - tr.w * uj.y;
        float epy = tr.z * uj.y + tr.w * uj.x;
        float dx = ui.x - epx, dy = ui.y - epy;
        // new row i
        ui.x = CHALF * (ui.x + epx);
        ui.y = CHALF * (ui.y + epy);
        // new row j = C * e^{i th} * (ui_old - e^{i phi} uj)
        float2 nj;
        nj.x = CHALF * (tr.x * dx - tr.y * dy);
        nj.y = CHALF * (tr.y * dx + tr.x * dy);
        sU[j * NF + t] = nj;
        if (++j == NF) {
            sU[i * NF + t] = ui;         // row i is final
            ++i;
            j = i + 1;
            if (i < NF) ui = sU[i * NF + t];
        }
    }
    // apply output phases (row scaling) and write U^T
    for (int r = 0; r < NF; ++r) {
        float so, co;
        sincosf(ophase[l * NF + r], &so, &co);
        float2 v = sU[r * NF + t];
        g_UT[l * NF * NF + t * NF + r] =
            make_float2(co * v.x - so * v.y, co * v.y + so * v.x);
    }
}

// ---------------------------------------------------------------------------
// Kernel B: fully fused main kernel.
// 128 batch rows per block, 256 threads.
// Complex GEMM micro-tile: 8 rows x 4 cols per thread.
// Shared: field ping (64KB) + field pong (64KB) + weight region (34KB).
// ---------------------------------------------------------------------------
__global__ __launch_bounds__(TPB, 1)
void ficonn_main(const float* __restrict__ x,
                 const float* __restrict__ beta_param,
                 const float* __restrict__ det0,
                 const float* __restrict__ W1, const float* __restrict__ b1,
                 const float* __restrict__ W2, const float* __restrict__ b2,
                 const float* __restrict__ W3, const float* __restrict__ b3,
                 float* __restrict__ out)
{
    extern __shared__ char smem[];
    float2* bufA = (float2*)smem;                 // 128*64 complex = 64KB
    float2* bufB = (float2*)(smem + 65536);       // 64KB
    float*  sWf  = (float*)(smem + 131072);       // 34816B weight region
    float2* sUT  = (float2*)sWf;                  // alias for unitary stage

    const int t  = threadIdx.x;
    const int rt = t >> 4;           // 0..15
    const int ct = t & 15;           // 0..15
    const int r0 = rt * 8;
    const int c0 = ct * 4;
    const long base = (long)blockIdx.x * TILE_R;

    // ---- load x tile into bufA as complex (imag = 0), vectorized ----
    {
        const float4* xv = (const float4*)(x + base * NF);
        float4* av = (float4*)bufA;
        for (int idx = t; idx < TILE_R * (NF / 4); idx += TPB) {
            float4 v = xv[idx];
            av[idx * 2 + 0] = make_float4(v.x, 0.f, v.y, 0.f);
            av[idx * 2 + 1] = make_float4(v.z, 0.f, v.w, 0.f);
        }
    }
    // ---- load U^T layer 0 ----
    {
        const float4* gu = (const float4*)g_UT;
        float4* su = (float4*)sUT;
        for (int idx = t; idx < (NF * NF) / 2; idx += TPB) su[idx] = gu[idx];
    }

    float2* cur = bufA;
    float2* nxt = bufB;

    for (int l = 0; l < NL; ++l) {
        __syncthreads();   // field + U^T ready

        float2 acc[8][4];
        #pragma unroll
        for (int p = 0; p < 8; ++p)
            #pragma unroll
            for (int q = 0; q < 4; ++q) acc[p][q] = make_float2(0.f, 0.f);

        #pragma unroll 2
        for (int j = 0; j < NF; ++j) {
            const float4 u01 = *(const float4*)(sUT + j * NF + c0);
            const float4 u23 = *(const float4*)(sUT + j * NF + c0 + 2);
            const float ux[4] = {u01.x, u01.z, u23.x, u23.z};
            const float uy[4] = {u01.y, u01.w, u23.y, u23.w};
            #pragma unroll
            for (int p = 0; p < 8; ++p) {
                const float2 f = cur[(r0 + p) * NF + j];
                #pragma unroll
                for (int q = 0; q < 4; ++q) {
                    acc[p][q].x = fmaf(ux[q], f.x, acc[p][q].x);
                    acc[p][q].x = fmaf(-uy[q], f.y, acc[p][q].x);
                    acc[p][q].y = fmaf(ux[q], f.y, acc[p][q].y);
                    acc[p][q].y = fmaf(uy[q], f.x, acc[p][q].y);
                }
            }
        }

        if (l < NL - 1) {
            // ---- nofu nonlinearity ----
            float sqq[4], kkq[4], d0q[4];
            #pragma unroll
            for (int q = 0; q < 4; ++q) {
                int c = c0 + q;
                float bp   = beta_param[l * NF + c];
                float beta = 1.f / (1.f + expf(-bp));
                sqq[q] = sqrtf(fmaxf(1.f - beta, 0.f));
                kkq[q] = 0.001f * 0.8f * beta;          // SENS*RESP*beta
                d0q[q] = det0[l * NF + c];
            }
            #pragma unroll
            for (int p = 0; p < 8; ++p) {
                float ox[4], oy[4];
                #pragma unroll
                for (int q = 0; q < 4; ++q) {
                    float fx = acc[p][q].x, fy = acc[p][q].y;
                    float pw = fx * fx + fy * fy;
                    float det = fmaf(kkq[q], pw, d0q[q]);
                    float s = sqq[q] * GAM / fmaf(det, det, GAM2);
                    ox[q] = s * fmaf(fy, det, fx * GAM);
                    oy[q] = s * fmaf(-fx, det, fy * GAM);
                }
                *(float4*)(nxt + (r0 + p) * NF + c0)     = make_float4(ox[0], oy[0], ox[1], oy[1]);
                *(float4*)(nxt + (r0 + p) * NF + c0 + 2) = make_float4(ox[2], oy[2], ox[3], oy[3]);
            }
        } else {
            // ---- final |field|^2 ----
            float* pw = (float*)nxt;
            #pragma unroll
            for (int p = 0; p < 8; ++p) {
                float4 v;
                v.x = acc[p][0].x * acc[p][0].x + acc[p][0].y * acc[p][0].y;
                v.y = acc[p][1].x * acc[p][1].x + acc[p][1].y * acc[p][1].y;
                v.z = acc[p][2].x * acc[p][2].x + acc[p][2].y * acc[p][2].y;
                v.w = acc[p][3].x * acc[p][3].x + acc[p][3].y * acc[p][3].y;
                *(float4*)(pw + (r0 + p) * NF + c0) = v;
            }
        }

        __syncthreads();   // all reads of cur/sUT done, nxt fully written

        if (l < NL - 1) {
            const float4* gu = (const float4*)(g_UT + (l + 1) * NF * NF);
            float4* su = (float4*)sUT;
            for (int idx = t; idx < (NF * NF) / 2; idx += TPB) su[idx] = gu[idx];
        }
        float2* tmp = cur; cur = nxt; nxt = tmp;
    }

    // ================= MLP head =================
    float* sPow = (float*)cur;   // 128x64 power (stride 64)
    float* sH1  = (float*)nxt;   // will hold h1 128x128 (stride 128)

    // W1 (128x64) -> transposed padded: sWf[j*132 + m]
    for (int idx = t; idx < 128 * 64; idx += TPB) {
        int m = idx >> 6, j = idx & 63;
        sWf[j * 132 + m] = W1[idx];
    }
    __syncthreads();

    // GEMM1: h1[r][m] = relu(b1[m] + sum_j P[r][j] * W1[m][j]); thread tile 8x8
    {
        const int m0 = ct * 8;
        float acc[8][8];
        #pragma unroll
        for (int p = 0; p < 8; ++p)
            #pragma unroll
            for (int q = 0; q < 8; ++q) acc[p][q] = 0.f;

        #pragma unroll 2
        for (int j = 0; j < 64; ++j) {
            float4 w0 = *(const float4*)(sWf + j * 132 + m0);
            float4 w1 = *(const float4*)(sWf + j * 132 + m0 + 4);
            float wv[8] = {w0.x, w0.y, w0.z, w0.w, w1.x, w1.y, w1.z, w1.w};
            #pragma unroll
            for (int p = 0; p < 8; ++p) {
                float pv = sPow[(r0 + p) * 64 + j];
                #pragma unroll
                for (int q = 0; q < 8; ++q) acc[p][q] = fmaf(pv, wv[q], acc[p][q]);
            }
        }
        float bb[8];
        #pragma unroll
        for (int q = 0; q < 8; ++q) bb[q] = b1[m0 + q];
        #pragma unroll
        for (int p = 0; p < 8; ++p) {
            float4 o0, o1;
            o0.x = fmaxf(acc[p][0] + bb[0], 0.f);
            o0.y = fmaxf(acc[p][1] + bb[1], 0.f);
            o0.z = fmaxf(acc[p][2] + bb[2], 0.f);
            o0.w = fmaxf(acc[p][3] + bb[3], 0.f);
            o1.x = fmaxf(acc[p][4] + bb[4], 0.f);
            o1.y = fmaxf(acc[p][5] + bb[5], 0.f);
            o1.z = fmaxf(acc[p][6] + bb[6], 0.f);
            o1.w = fmaxf(acc[p][7] + bb[7], 0.f);
            *(float4*)(sH1 + (r0 + p) * 128 + m0)     = o0;
            *(float4*)(sH1 + (r0 + p) * 128 + m0 + 4) = o1;
        }
    }
    __syncthreads();

    // W2 (64x128) -> transposed padded: sWf[m*68 + n]
    for (int idx = t; idx < 64 * 128; idx += TPB) {
        int n = idx >> 7, m = idx & 127;
        sWf[m * 68 + n] = W2[idx];
    }
    __syncthreads();

    // GEMM2: h2[r][n] = relu(b2[n] + sum_m h1[r][m] * W2[n][m]); thread tile 8x4
    float* sH2 = sPow;   // reuse power region, stride 68
    {
        const int n0 = ct * 4;
        float acc[8][4];
        #pragma unroll
        for (int p = 0; p < 8; ++p)
            #pragma unroll
            for (int q = 0; q < 4; ++q) acc[p][q] = 0.f;

        #pragma unroll 2
        for (int m = 0; m < 128; ++m) {
            float4 w = *(const float4*)(sWf + m * 68 + n0);
            #pragma unroll
            for (int p = 0; p < 8; ++p) {
                float hv = sH1[(r0 + p) * 128 + m];
                acc[p][0] = fmaf(hv, w.x, acc[p][0]);
                acc[p][1] = fmaf(hv, w.y, acc[p][1]);
                acc[p][2] = fmaf(hv, w.z, acc[p][2]);
                acc[p][3] = fmaf(hv, w.w, acc[p][3]);
            }
        }
        float bb[4];
        #pragma unroll
        for (int q = 0; q < 4; ++q) bb[q] = b2[n0 + q];
        #pragma unroll
        for (int p = 0; p < 8; ++p) {
            float4 o;
            o.x = fmaxf(acc[p][0] + bb[0], 0.f);
            o.y = fmaxf(acc[p][1] + bb[1], 0.f);
            o.z = fmaxf(acc[p][2] + bb[2], 0.f);
            o.w = fmaxf(acc[p][3] + bb[3], 0.f);
            *(float4*)(sH2 + (r0 + p) * 68 + n0) = o;
        }
    }
    __syncthreads();

    // W3 (12x64) into weight region
    for (int idx = t; idx < NCLS * 64; idx += TPB) sWf[idx] = W3[idx];
    __syncthreads();

    // GEMM3: out[r][c] = b3[c] + sum_j h2[r][j] * W3[c][j]
    {
        const int r  = t >> 1;
        const int ch = (t & 1) * 6;
        float acc[6] = {0.f, 0.f, 0.f, 0.f, 0.f, 0.f};
        #pragma unroll 4
        for (int j = 0; j < 64; ++j) {
            float h = sH2[r * 68 + j];
            #pragma unroll
            for (int q = 0; q < 6; ++q)
                acc[q] = fmaf(h, sWf[(ch + q) * 64 + j], acc[q]);
        }
        #pragma unroll
        for (int q = 0; q < 6; ++q)
            out[(base + r) * NCLS + ch + q] = acc[q] + b3[ch + q];
    }
}

// ---------------------------------------------------------------------------
extern "C" void kernel_launch(void* const* d_in, const int* in_sizes, int n_in,
                              void* d_out, int out_size) {
    const float* x     = (const float*)d_in[0];
    const float* mzi   = (const float*)d_in[1];
    const float* oph   = (const float*)d_in[2];
    const float* betap = (const float*)d_in[3];
    const float* det0  = (const float*)d_in[4];
    const float* W1    = (const float*)d_in[5];
    const float* b1    = (const float*)d_in[6];
    const float* W2    = (const float*)d_in[7];
    const float* b2    = (const float*)d_in[8];
    const float* W3    = (const float*)d_in[9];
    const float* b3    = (const float*)d_in[10];
    float* out = (float*)d_out;

    const int rows = in_sizes[0] / NF;          // 262144
    const int grid = rows / TILE_R;             // 2048
    const int smem = 65536 * 2 + 34816;         // 165888 bytes

    cudaFuncSetAttribute(ficonn_main, cudaFuncAttributeMaxDynamicSharedMemorySize, smem);

    trig_kernel<<<(NL * NMZI + 255) / 256, 256>>>(mzi);
    build_unitaries<<<NL, 64>>>(oph);
    ficonn_main<<<grid, TPB, smem>>>(x, betap, det0, W1, b1, W2, b2, W3, b3, out);
}